// round 13
// baseline (speedup 1.0000x reference)
#include <cuda_runtime.h>
#include <cuda_fp16.h>
#include <cstdint>
#include <cstddef>

#define NN 16384
#define DD 512
#define WPR 256    // half2 words per row (DD/2)
#define NSEG 128   // partial segments per direction (one per GEMM block row/col)
#define NGRP 8     // level-1 merge groups
#define SPG  16    // segments per group

// ---------------- scratch (device globals; sanctioned) ------------------------
__device__ float    g_simT[(size_t)NN * NN]; // simT[i][j] = <R_i, L_j>
__device__ uint32_t g_Lhi[(size_t)NN * WPR];
__device__ uint32_t g_Llo[(size_t)NN * WPR];
__device__ uint32_t g_Rhi[(size_t)NN * WPR];
__device__ float    g_rpart[NSEG][NN][10];   // row top-10 partials (seg = n-block)
__device__ float    g_cpart[NSEG][NN][10];   // col top-10 partials (seg = m-block)
__device__ float    g_rmid[NGRP][NN][10];
__device__ float    g_cmid[NGRP][NN][10];
__device__ float    g_RL[NN];
__device__ float    g_P [NN];

// ---------------- precompute: fp16 hi/lo split, packed half2 ------------------
__global__ __launch_bounds__(256)
void cvt_hl(const float* __restrict__ L, const float* __restrict__ R) {
    const size_t w = (size_t)blockIdx.x * 256 + threadIdx.x;
    if (blockIdx.y == 0) {
        float2 v = ((const float2*)L)[w];
        __half hx = __float2half_rn(v.x);
        __half hy = __float2half_rn(v.y);
        float lx = v.x - __half2float(hx);
        float ly = v.y - __half2float(hy);
        __half2 hhi = __halves2half2(hx, hy);
        __half2 hlo = __floats2half2_rn(lx, ly);
        g_Lhi[w] = *(uint32_t*)&hhi;
        g_Llo[w] = *(uint32_t*)&hlo;
    } else {
        float2 v = ((const float2*)R)[w];
        __half2 hhi = __floats2half2_rn(v.x, v.y);
        g_Rhi[w] = *(uint32_t*)&hhi;
    }
}

// ---------------- helpers ----------------------------------------------------
__device__ __forceinline__ void mma_f16(float* c, const uint32_t* a, uint32_t b0, uint32_t b1) {
    asm volatile(
        "mma.sync.aligned.m16n8k16.row.col.f32.f16.f16.f32 "
        "{%0,%1,%2,%3}, {%4,%5,%6,%7}, {%8,%9}, {%0,%1,%2,%3};"
        : "+f"(c[0]), "+f"(c[1]), "+f"(c[2]), "+f"(c[3])
        : "r"(a[0]), "r"(a[1]), "r"(a[2]), "r"(a[3]), "r"(b0), "r"(b1));
}

__device__ __forceinline__ void ldsm4(uint32_t* r, uint32_t addr) {
    asm volatile("ldmatrix.sync.aligned.m8n8.x4.shared.b16 {%0,%1,%2,%3}, [%4];"
                 : "=r"(r[0]), "=r"(r[1]), "=r"(r[2]), "=r"(r[3]) : "r"(addr));
}

__device__ __forceinline__ void insert10(float* t, float v) {
    if (v > t[0]) {
        t[0] = v;
#pragma unroll
        for (int i = 0; i < 9; i++) {
            if (t[i] > t[i + 1]) { float tmp = t[i]; t[i] = t[i + 1]; t[i + 1] = tmp; }
        }
    }
}

#define SENT (-1e30f)

// ---------------- GEMM + fused top-k partials ---------------------------------
// simT = R . L^T (2-term fp16: Ahi*Bhi + Ahi*Blo).
// Epilogue computes per-block row/col top-10 partials from registers.
#define BM 128
#define BN 128
#define SSTW 12
#define CSZ (128 * SSTW)
#define EST 132    // staging row stride (floats)

__global__ __launch_bounds__(256, 2)
void gemm_hl() {
    __shared__ uint32_t S[2][3][CSZ];   // 36.9 KB GEMM buffers
    __shared__ float    E[32 * EST];    // 16.9 KB epilogue staging slice

    const int bm = blockIdx.y * BM;
    const int bn = blockIdx.x * BN;
    const int tid  = threadIdx.x;
    const int warp = tid >> 5;
    const int lane = tid & 31;
    const int wm = (warp & 3) * 32;
    const int wn = (warp >> 2) * 64;

    const int l_row = tid >> 1;
    const int l_wb  = (tid & 1) * 4;

    const uint4* gAhi = (const uint4*)g_Rhi;
    const uint4* gBhi = (const uint4*)g_Lhi;
    const uint4* gBlo = (const uint4*)g_Llo;

    uint4 pa_h, pb_h, pb_l;
    auto load_regs = [&](int c) {
        size_t ia = ((size_t)(bm + l_row) * WPR + c * 8 + l_wb) >> 2;
        size_t ib = ((size_t)(bn + l_row) * WPR + c * 8 + l_wb) >> 2;
        pa_h = gAhi[ia];
        pb_h = gBhi[ib]; pb_l = gBlo[ib];
    };
    auto store_smem = [&](int buf) {
        int off = l_row * SSTW + l_wb;
        *(uint4*)&S[buf][0][off] = pa_h;
        *(uint4*)&S[buf][1][off] = pb_h;
        *(uint4*)&S[buf][2][off] = pb_l;
    };

    const uint32_t sb = (uint32_t)__cvta_generic_to_shared(&S[0][0][0]);
    const uint32_t aW = (uint32_t)((wm + (lane & 15)) * SSTW + ((lane >> 4) << 2));
    const uint32_t bW = (uint32_t)((wn + (lane & 7) + ((lane >> 4) << 3)) * SSTW +
                                   (((lane >> 3) & 1) << 2));

    float acc[2][8][4];
#pragma unroll
    for (int im = 0; im < 2; im++)
#pragma unroll
        for (int in = 0; in < 8; in++)
#pragma unroll
            for (int q = 0; q < 4; q++) acc[im][in][q] = 0.0f;

    load_regs(0);
    store_smem(0);
    __syncthreads();

    const int NCHUNK = DD / 16;
    for (int c = 0; c < NCHUNK; c++) {
        if (c + 1 < NCHUNK) load_regs(c + 1);

        const uint32_t bufoff = (uint32_t)((c & 1) * 3 * CSZ);
        const uint32_t aHiA = sb + (bufoff + 0 * CSZ + aW) * 4;
        const uint32_t bHiA = sb + (bufoff + 1 * CSZ + bW) * 4;
        const uint32_t bLoA = sb + (bufoff + 2 * CSZ + bW) * 4;

        uint32_t afh[2][4];
#pragma unroll
        for (int im = 0; im < 2; im++)
            ldsm4(afh[im], aHiA + im * 16 * SSTW * 4);

#pragma unroll
        for (int inp = 0; inp < 4; inp++) {
            uint32_t bh[4], bl[4];
            ldsm4(bh, bHiA + inp * 16 * SSTW * 4);
            ldsm4(bl, bLoA + inp * 16 * SSTW * 4);
#pragma unroll
            for (int s = 0; s < 2; s++) {
                const int in = inp * 2 + s;
#pragma unroll
                for (int im = 0; im < 2; im++) {
                    mma_f16(acc[im][in], afh[im], bh[2 * s], bh[2 * s + 1]);
                    mma_f16(acc[im][in], afh[im], bl[2 * s], bl[2 * s + 1]);
                }
            }
        }

        if (c + 1 < NCHUNK) store_smem((c + 1) & 1);
        __syncthreads();
    }

    // ---- write simT ----
#pragma unroll
    for (int im = 0; im < 2; im++) {
#pragma unroll
        for (int in = 0; in < 8; in++) {
            int m = bm + wm + im * 16 + (lane >> 2);
            int n = bn + wn + in * 8 + 2 * (lane & 3);
            *(float2*)&g_simT[(size_t)m * NN + n]       = make_float2(acc[im][in][0], acc[im][in][1]);
            *(float2*)&g_simT[(size_t)(m + 8) * NN + n] = make_float2(acc[im][in][2], acc[im][in][3]);
        }
    }

    // ---- fused top-k partials: 4 slices of 32 rows ----
    float tkc[10];   // column list (threads 0..127 own column tid)
#pragma unroll
    for (int i = 0; i < 10; i++) tkc[i] = SENT;

    const int mrow = lane >> 2;

#pragma unroll 1
    for (int s = 0; s < 4; s++) {
        __syncthreads();   // E free (previous slice consumed / mainloop done)
        if ((warp & 3) == s) {
#pragma unroll
            for (int im = 0; im < 2; im++)
#pragma unroll
                for (int in = 0; in < 8; in++)
#pragma unroll
                    for (int qp = 0; qp < 2; qp++) {
                        int rl = im * 16 + mrow + 8 * qp;
                        int cl = wn + in * 8 + 2 * (lane & 3);
                        *(float2*)&E[rl * EST + cl] =
                            make_float2(acc[im][in][qp * 2], acc[im][in][qp * 2 + 1]);
                    }
        }
        __syncthreads();

        // col partials: thread t<128 owns column t, walks 32 rows
        if (tid < 128) {
#pragma unroll 1
            for (int r = 0; r < 32; r++) {
                float v = E[r * EST + tid];
                insert10(tkc, v);
            }
        }

        // row partials: 8 lanes per row (tid>>3 = row, tid&7 = 16-col chunk)
        {
            const int rl = tid >> 3;
            const int ch = tid & 7;
            float tk[10];
#pragma unroll
            for (int i = 0; i < 10; i++) tk[i] = SENT;
            const float* er = &E[rl * EST + ch * 16];
#pragma unroll
            for (int j = 0; j < 16; j++) insert10(tk, er[j]);
            // butterfly merge among the 8 lanes of this row (snapshot then insert)
#pragma unroll
            for (int st = 4; st >= 1; st >>= 1) {
                float rv[10];
#pragma unroll
                for (int i = 0; i < 10; i++)
                    rv[i] = __shfl_xor_sync(0xffffffffu, tk[i], st);
#pragma unroll
                for (int i = 0; i < 10; i++) insert10(tk, rv[i]);
            }
            if (ch == 0) {
                int grow = bm + s * 32 + rl;
#pragma unroll
                for (int i = 0; i < 10; i++) g_rpart[blockIdx.x][grow][i] = tk[i];
            }
        }
    }

    if (tid < 128) {
#pragma unroll
        for (int i = 0; i < 10; i++) g_cpart[blockIdx.y][bn + tid][i] = tkc[i];
    }
}

// ---------------- merge kernels (two-level, screened) -------------------------
__global__ __launch_bounds__(256)
void merge_r_l1() {
    const int row = blockIdx.x * 256 + threadIdx.x;
    const int g   = blockIdx.y;
    float t[10];
#pragma unroll
    for (int i = 0; i < 10; i++) t[i] = SENT;
#pragma unroll 1
    for (int s = 0; s < SPG; s++) {
        const float* p = g_rpart[g * SPG + s][row];
        if (p[9] > t[0])
#pragma unroll
            for (int i = 0; i < 10; i++) insert10(t, p[i]);
    }
#pragma unroll
    for (int i = 0; i < 10; i++) g_rmid[g][row][i] = t[i];
}

__global__ __launch_bounds__(256)
void merge_r_l2() {
    const int row = blockIdx.x * 256 + threadIdx.x;
    float t[10];
#pragma unroll
    for (int i = 0; i < 10; i++) t[i] = g_rmid[0][row][i];
#pragma unroll 1
    for (int g = 1; g < NGRP; g++) {
        const float* p = g_rmid[g][row];
        if (p[9] > t[0])
#pragma unroll
            for (int i = 0; i < 10; i++) insert10(t, p[i]);
    }
    float sum = 0.0f;
#pragma unroll
    for (int i = 0; i < 10; i++) sum += t[i];
    g_RL[row] = sum * 0.1f;
}

__global__ __launch_bounds__(256)
void merge_c_l1() {
    const int col = blockIdx.x * 256 + threadIdx.x;
    const int g   = blockIdx.y;
    float t[10];
#pragma unroll
    for (int i = 0; i < 10; i++) t[i] = SENT;
#pragma unroll 1
    for (int s = 0; s < SPG; s++) {
        const float* p = g_cpart[g * SPG + s][col];
        if (p[9] > t[0])
#pragma unroll
            for (int i = 0; i < 10; i++) insert10(t, p[i]);
    }
#pragma unroll
    for (int i = 0; i < 10; i++) g_cmid[g][col][i] = t[i];
}

__global__ __launch_bounds__(256)
void merge_c_l2() {
    const int col = blockIdx.x * 256 + threadIdx.x;
    float t[10];
#pragma unroll
    for (int i = 0; i < 10; i++) t[i] = g_cmid[0][col][i];
#pragma unroll 1
    for (int g = 1; g < NGRP; g++) {
        const float* p = g_cmid[g][col];
        if (p[9] > t[0])
#pragma unroll
            for (int i = 0; i < 10; i++) insert10(t, p[i]);
    }
    float sum = 0.0f;
#pragma unroll
    for (int i = 0; i < 10; i++) sum += t[i];
    g_P[col] = sum * 0.1f + g_RL[col];   // P = LR + RL (RL ready)
}

// ---------------- rank + top1 over csls rows ---------------------------------
__global__ __launch_bounds__(256)
void rank_top1(float* __restrict__ ranks, float* __restrict__ top1) {
    __shared__ int   s_gt[256];
    __shared__ int   s_eq[256];
    __shared__ float s_mx[256];

    const int i   = blockIdx.x;
    const int tid = threadIdx.x;
    const float* prow = g_simT + (size_t)i * NN;
    const float d = 2.0f * prow[i] - g_P[i];

    int cnt_gt = 0, cnt_eq = 0;
    float mx = SENT;

    const float4* pv = (const float4*)prow;
    const float4* qv = (const float4*)g_P;
    for (int j4 = tid; j4 < NN / 4; j4 += 256) {
        float4 v = pv[j4];
        float4 q = qv[j4];
        int j = j4 * 4;
        float c0 = 2.0f * v.x - q.x;
        float c1 = 2.0f * v.y - q.y;
        float c2 = 2.0f * v.z - q.z;
        float c3 = 2.0f * v.w - q.w;
        cnt_gt += (c0 > d) + (c1 > d) + (c2 > d) + (c3 > d);
        if (c0 == d && (j + 0) < i) cnt_eq++;
        if (c1 == d && (j + 1) < i) cnt_eq++;
        if (c2 == d && (j + 2) < i) cnt_eq++;
        if (c3 == d && (j + 3) < i) cnt_eq++;
        mx = fmaxf(mx, fmaxf(fmaxf(c0, c1), fmaxf(c2, c3)));
    }

    s_gt[tid] = cnt_gt; s_eq[tid] = cnt_eq; s_mx[tid] = mx;
    __syncthreads();
    for (int str = 128; str > 0; str >>= 1) {
        if (tid < str) {
            s_gt[tid] += s_gt[tid + str];
            s_eq[tid] += s_eq[tid + str];
            s_mx[tid] = fmaxf(s_mx[tid], s_mx[tid + str]);
        }
        __syncthreads();
    }
    if (tid == 0) {
        ranks[i] = (float)(s_gt[0] + s_eq[0]);
        top1[i]  = s_mx[0];
    }
}

// ---------------- launch ------------------------------------------------------
extern "C" void kernel_launch(void* const* d_in, const int* in_sizes, int n_in,
                              void* d_out, int out_size) {
    const float* L = (const float*)d_in[0];
    const float* R = (const float*)d_in[1];

    dim3 cgrid(NN * WPR / 256, 2);
    cvt_hl<<<cgrid, 256>>>(L, R);

    dim3 grid(NN / BN, NN / BM);
    gemm_hl<<<grid, 256>>>();   // GEMM + fused top-k partials

    merge_r_l1<<<dim3(NN / 256, NGRP), 256>>>();
    merge_r_l2<<<NN / 256, 256>>>();
    merge_c_l1<<<dim3(NN / 256, NGRP), 256>>>();
    merge_c_l2<<<NN / 256, 256>>>();

    float* ranks = (float*)d_out;
    float* top1  = (float*)d_out + NN;
    rank_top1<<<NN, 256>>>(ranks, top1);
}

// round 14
// speedup vs baseline: 1.1524x; 1.1524x over previous
#include <cuda_runtime.h>
#include <cuda_fp16.h>
#include <cstdint>
#include <cstddef>

#define NN 16384
#define DD 512
#define WPR 256   // half2 words per row (DD/2)
#define NSEG 16   // column-topk row segments
#define NSTRIP 4  // GEMM row strips (pipeline stages)

// ---------------- scratch (device globals; sanctioned) ------------------------
__device__ float    g_simT[(size_t)NN * NN]; // simT[i][j] = <R_i, L_j>
__device__ uint32_t g_Lhi[(size_t)NN * WPR];
__device__ uint32_t g_Llo[(size_t)NN * WPR];
__device__ uint32_t g_Rhi[(size_t)NN * WPR];
__device__ float    g_part[NSEG][NN][10];    // per-segment column top-10
__device__ float    g_RL[NN];
__device__ float    g_P [NN];

// ---------------- precompute: fp16 hi/lo split, packed half2 ------------------
__global__ __launch_bounds__(256)
void cvt_hl(const float* __restrict__ L, const float* __restrict__ R) {
    const size_t w = (size_t)blockIdx.x * 256 + threadIdx.x;
    if (blockIdx.y == 0) {
        float2 v = ((const float2*)L)[w];
        __half hx = __float2half_rn(v.x);
        __half hy = __float2half_rn(v.y);
        float lx = v.x - __half2float(hx);
        float ly = v.y - __half2float(hy);
        __half2 hhi = __halves2half2(hx, hy);
        __half2 hlo = __floats2half2_rn(lx, ly);
        g_Lhi[w] = *(uint32_t*)&hhi;
        g_Llo[w] = *(uint32_t*)&hlo;
    } else {
        float2 v = ((const float2*)R)[w];
        __half2 hhi = __floats2half2_rn(v.x, v.y);
        g_Rhi[w] = *(uint32_t*)&hhi;
    }
}

// ---------------- fp16 MMA + ldmatrix ----------------------------------------
__device__ __forceinline__ void mma_f16(float* c, const uint32_t* a, uint32_t b0, uint32_t b1) {
    asm volatile(
        "mma.sync.aligned.m16n8k16.row.col.f32.f16.f16.f32 "
        "{%0,%1,%2,%3}, {%4,%5,%6,%7}, {%8,%9}, {%0,%1,%2,%3};"
        : "+f"(c[0]), "+f"(c[1]), "+f"(c[2]), "+f"(c[3])
        : "r"(a[0]), "r"(a[1]), "r"(a[2]), "r"(a[3]), "r"(b0), "r"(b1));
}

__device__ __forceinline__ void ldsm4(uint32_t* r, uint32_t addr) {
    asm volatile("ldmatrix.sync.aligned.m8n8.x4.shared.b16 {%0,%1,%2,%3}, [%4];"
                 : "=r"(r[0]), "=r"(r[1]), "=r"(r[2]), "=r"(r[3]) : "r"(addr));
}

// ---------------- GEMM: simT = R . L^T  (2-term fp16 split), row strip --------
#define BM 128
#define BN 128
#define SSTW 12
#define CSZ (128 * SSTW)

__global__ __launch_bounds__(256, 2)
void gemm_hl(int strip) {
    __shared__ uint32_t S[2][3][CSZ];   // [buf][Ahi,Bhi,Blo]

    const int bm = (blockIdx.y + strip * (NN / BM / NSTRIP)) * BM;
    const int bn = blockIdx.x * BN;
    const int tid  = threadIdx.x;
    const int warp = tid >> 5;
    const int lane = tid & 31;
    const int wm = (warp & 3) * 32;
    const int wn = (warp >> 2) * 64;

    const int l_row = tid >> 1;
    const int l_wb  = (tid & 1) * 4;

    const uint4* gAhi = (const uint4*)g_Rhi;
    const uint4* gBhi = (const uint4*)g_Lhi;
    const uint4* gBlo = (const uint4*)g_Llo;

    uint4 pa_h, pb_h, pb_l;
    auto load_regs = [&](int c) {
        size_t ia = ((size_t)(bm + l_row) * WPR + c * 8 + l_wb) >> 2;
        size_t ib = ((size_t)(bn + l_row) * WPR + c * 8 + l_wb) >> 2;
        pa_h = gAhi[ia];
        pb_h = gBhi[ib]; pb_l = gBlo[ib];
    };
    auto store_smem = [&](int buf) {
        int off = l_row * SSTW + l_wb;
        *(uint4*)&S[buf][0][off] = pa_h;
        *(uint4*)&S[buf][1][off] = pb_h;
        *(uint4*)&S[buf][2][off] = pb_l;
    };

    const uint32_t sb = (uint32_t)__cvta_generic_to_shared(&S[0][0][0]);
    const uint32_t aW = (uint32_t)((wm + (lane & 15)) * SSTW + ((lane >> 4) << 2));
    const uint32_t bW = (uint32_t)((wn + (lane & 7) + ((lane >> 4) << 3)) * SSTW +
                                   (((lane >> 3) & 1) << 2));

    float acc[2][8][4];
#pragma unroll
    for (int im = 0; im < 2; im++)
#pragma unroll
        for (int in = 0; in < 8; in++)
#pragma unroll
            for (int q = 0; q < 4; q++) acc[im][in][q] = 0.0f;

    load_regs(0);
    store_smem(0);
    __syncthreads();

    const int NCHUNK = DD / 16;
    for (int c = 0; c < NCHUNK; c++) {
        if (c + 1 < NCHUNK) load_regs(c + 1);

        const uint32_t bufoff = (uint32_t)((c & 1) * 3 * CSZ);
        const uint32_t aHiA = sb + (bufoff + 0 * CSZ + aW) * 4;
        const uint32_t bHiA = sb + (bufoff + 1 * CSZ + bW) * 4;
        const uint32_t bLoA = sb + (bufoff + 2 * CSZ + bW) * 4;

        uint32_t afh[2][4];
#pragma unroll
        for (int im = 0; im < 2; im++)
            ldsm4(afh[im], aHiA + im * 16 * SSTW * 4);

#pragma unroll
        for (int inp = 0; inp < 4; inp++) {
            uint32_t bh[4], bl[4];
            ldsm4(bh, bHiA + inp * 16 * SSTW * 4);
            ldsm4(bl, bLoA + inp * 16 * SSTW * 4);
#pragma unroll
            for (int s = 0; s < 2; s++) {
                const int in = inp * 2 + s;
#pragma unroll
                for (int im = 0; im < 2; im++) {
                    mma_f16(acc[im][in], afh[im], bh[2 * s], bh[2 * s + 1]);
                    mma_f16(acc[im][in], afh[im], bl[2 * s], bl[2 * s + 1]);
                }
            }
        }

        if (c + 1 < NCHUNK) store_smem((c + 1) & 1);
        __syncthreads();
    }

#pragma unroll
    for (int im = 0; im < 2; im++) {
#pragma unroll
        for (int in = 0; in < 8; in++) {
            int m = bm + wm + im * 16 + (lane >> 2);
            int n = bn + wn + in * 8 + 2 * (lane & 3);
            *(float2*)&g_simT[(size_t)m * NN + n]       = make_float2(acc[im][in][0], acc[im][in][1]);
            *(float2*)&g_simT[(size_t)(m + 8) * NN + n] = make_float2(acc[im][in][2], acc[im][in][3]);
        }
    }
}

// ---------------- top-10 insertion (t ascending; t[0] = current min) ----------
__device__ __forceinline__ void insert10(float* t, float v) {
    if (v > t[0]) {
        t[0] = v;
#pragma unroll
        for (int i = 0; i < 9; i++) {
            if (t[i] > t[i + 1]) { float tmp = t[i]; t[i] = t[i + 1]; t[i + 1] = tmp; }
        }
    }
}

#define SENT (-1e30f)

// ---------------- RL: per-row top-10 mean (strip of 4096 rows) ----------------
__global__ __launch_bounds__(256)
void row_topk_mean(int strip) {
    __shared__ float s[256 * 10];
    const int row = blockIdx.x + strip * (NN / NSTRIP);
    const int tid = threadIdx.x;
    const float4* p = (const float4*)(g_simT + (size_t)row * NN);

    float t[10];
#pragma unroll
    for (int i = 0; i < 10; i++) t[i] = SENT;

    for (int j = tid; j < NN / 4; j += 256) {
        float4 v = p[j];
        insert10(t, v.x); insert10(t, v.y); insert10(t, v.z); insert10(t, v.w);
    }
#pragma unroll
    for (int i = 0; i < 10; i++) s[tid * 10 + i] = t[i];
    __syncthreads();

    if (tid < 32) {
#pragma unroll
        for (int i = 0; i < 10; i++) t[i] = s[tid * 10 + i];
        for (int src = tid + 32; src < 256; src += 32)
#pragma unroll
            for (int i = 0; i < 10; i++) insert10(t, s[src * 10 + i]);
#pragma unroll
        for (int i = 0; i < 10; i++) s[tid * 10 + i] = t[i];
    }
    __syncthreads();

    if (tid == 0) {
#pragma unroll
        for (int i = 0; i < 10; i++) t[i] = s[i];
        for (int src = 1; src < 32; src++)
#pragma unroll
            for (int i = 0; i < 10; i++) insert10(t, s[src * 10 + i]);
        float sum = 0.0f;
#pragma unroll
        for (int i = 0; i < 10; i++) sum += t[i];
        g_RL[row] = sum * 0.1f;
    }
}

// ---------------- LR stage 1: per-segment column top-10 (strip segs) ----------
__global__ __launch_bounds__(256)
void col_topk_part(int strip) {
    const int col = blockIdx.x * 256 + threadIdx.x;
    const int seg = blockIdx.y + strip * (NSEG / NSTRIP);

    float t[10];
#pragma unroll
    for (int i = 0; i < 10; i++) t[i] = SENT;

    const float* base = g_simT + (size_t)seg * (NN / NSEG) * NN + col;
#pragma unroll 1
    for (int r = 0; r < NN / NSEG; r += 8) {
        float v0 = base[(size_t)(r + 0) * NN];
        float v1 = base[(size_t)(r + 1) * NN];
        float v2 = base[(size_t)(r + 2) * NN];
        float v3 = base[(size_t)(r + 3) * NN];
        float v4 = base[(size_t)(r + 4) * NN];
        float v5 = base[(size_t)(r + 5) * NN];
        float v6 = base[(size_t)(r + 6) * NN];
        float v7 = base[(size_t)(r + 7) * NN];
        insert10(t, v0); insert10(t, v1); insert10(t, v2); insert10(t, v3);
        insert10(t, v4); insert10(t, v5); insert10(t, v6); insert10(t, v7);
    }
#pragma unroll
    for (int i = 0; i < 10; i++) g_part[seg][col][i] = t[i];
}

// ---------------- LR stage 2: merge segments; P = LR + RL ---------------------
__global__ __launch_bounds__(256)
void col_topk_reduce() {
    const int col = blockIdx.x * 256 + threadIdx.x;
    float t[10];
#pragma unroll
    for (int i = 0; i < 10; i++) t[i] = g_part[0][col][i];
#pragma unroll 1
    for (int seg = 1; seg < NSEG; seg++) {
        if (g_part[seg][col][9] > t[0])
#pragma unroll
            for (int i = 0; i < 10; i++) insert10(t, g_part[seg][col][i]);
    }
    float sum = 0.0f;
#pragma unroll
    for (int i = 0; i < 10; i++) sum += t[i];
    g_P[col] = sum * 0.1f + g_RL[col];   // P = LR + RL
}

// ---------------- rank + top1 over csls rows ---------------------------------
__global__ __launch_bounds__(256)
void rank_top1(float* __restrict__ ranks, float* __restrict__ top1) {
    __shared__ int   s_gt[256];
    __shared__ int   s_eq[256];
    __shared__ float s_mx[256];

    const int i   = blockIdx.x;
    const int tid = threadIdx.x;
    const float* prow = g_simT + (size_t)i * NN;
    const float d = 2.0f * prow[i] - g_P[i];

    int cnt_gt = 0, cnt_eq = 0;
    float mx = SENT;

    const float4* pv = (const float4*)prow;
    const float4* qv = (const float4*)g_P;
    for (int j4 = tid; j4 < NN / 4; j4 += 256) {
        float4 v = pv[j4];
        float4 q = qv[j4];
        int j = j4 * 4;
        float c0 = 2.0f * v.x - q.x;
        float c1 = 2.0f * v.y - q.y;
        float c2 = 2.0f * v.z - q.z;
        float c3 = 2.0f * v.w - q.w;
        cnt_gt += (c0 > d) + (c1 > d) + (c2 > d) + (c3 > d);
        if (c0 == d && (j + 0) < i) cnt_eq++;
        if (c1 == d && (j + 1) < i) cnt_eq++;
        if (c2 == d && (j + 2) < i) cnt_eq++;
        if (c3 == d && (j + 3) < i) cnt_eq++;
        mx = fmaxf(mx, fmaxf(fmaxf(c0, c1), fmaxf(c2, c3)));
    }

    s_gt[tid] = cnt_gt; s_eq[tid] = cnt_eq; s_mx[tid] = mx;
    __syncthreads();
    for (int str = 128; str > 0; str >>= 1) {
        if (tid < str) {
            s_gt[tid] += s_gt[tid + str];
            s_eq[tid] += s_eq[tid + str];
            s_mx[tid] = fmaxf(s_mx[tid], s_mx[tid + str]);
        }
        __syncthreads();
    }
    if (tid == 0) {
        ranks[i] = (float)(s_gt[0] + s_eq[0]);
        top1[i]  = s_mx[0];
    }
}

// ---------------- launch: strip-pipelined fork/join ---------------------------
extern "C" void kernel_launch(void* const* d_in, const int* in_sizes, int n_in,
                              void* d_out, int out_size) {
    const float* L = (const float*)d_in[0];
    const float* R = (const float*)d_in[1];

    // Fresh side stream + events per call (kernel_launch runs only for the
    // correctness pass and the single capture pass; host-object leak is
    // bounded and device memory is untouched). Work per call is identical.
    cudaStream_t s1;
    cudaStreamCreateWithFlags(&s1, cudaStreamNonBlocking);
    cudaEvent_t ev[NSTRIP], evj;
    for (int g = 0; g < NSTRIP; g++) cudaEventCreateWithFlags(&ev[g], cudaEventDisableTiming);
    cudaEventCreateWithFlags(&evj, cudaEventDisableTiming);

    dim3 cgrid(NN * WPR / 256, 2);
    cvt_hl<<<cgrid, 256>>>(L, R);

    // GEMM strips on the main (capture) stream; event after each strip
    dim3 ggrid(NN / BN, NN / BM / NSTRIP);
    for (int g = 0; g < NSTRIP; g++) {
        gemm_hl<<<ggrid, 256>>>(g);
        cudaEventRecord(ev[g], 0);
    }

    // forked stream: top-k for strip g overlaps GEMM of strip g+1
    for (int g = 0; g < NSTRIP; g++) {
        cudaStreamWaitEvent(s1, ev[g], 0);
        row_topk_mean<<<NN / NSTRIP, 256, 0, s1>>>(g);
        col_topk_part<<<dim3(NN / 256, NSEG / NSTRIP), 256, 0, s1>>>(g);
    }
    cudaEventRecord(evj, s1);
    cudaStreamWaitEvent(0, evj, 0);   // join

    col_topk_reduce<<<NN / 256, 256>>>();

    float* ranks = (float*)d_out;
    float* top1  = (float*)d_out + NN;
    rank_top1<<<NN, 256>>>(ranks, top1);
}

// round 15
// speedup vs baseline: 1.3714x; 1.1900x over previous
#include <cuda_runtime.h>
#include <cuda_fp16.h>
#include <cstdint>
#include <cstddef>

#define NN 16384
#define DD 512
#define WPR 256   // half2 words per row (DD/2)
#define NSEG 16   // column-topk row segments

// ---------------- scratch (device globals; sanctioned) ------------------------
__device__ float    g_simT[(size_t)NN * NN]; // simT[i][j] = <R_i, L_j>
__device__ uint32_t g_Lhi[(size_t)NN * WPR];
__device__ uint32_t g_Llo[(size_t)NN * WPR];
__device__ uint32_t g_Rhi[(size_t)NN * WPR];
__device__ float    g_part[NSEG][NN][10];    // per-segment column top-10
__device__ float    g_RL[NN];
__device__ float    g_P [NN];

// ---------------- precompute: fp16 hi/lo split, packed half2 ------------------
__global__ __launch_bounds__(256)
void cvt_hl(const float* __restrict__ L, const float* __restrict__ R) {
    const size_t w = (size_t)blockIdx.x * 256 + threadIdx.x;
    if (blockIdx.y == 0) {
        float2 v = ((const float2*)L)[w];
        __half hx = __float2half_rn(v.x);
        __half hy = __float2half_rn(v.y);
        float lx = v.x - __half2float(hx);
        float ly = v.y - __half2float(hy);
        __half2 hhi = __halves2half2(hx, hy);
        __half2 hlo = __floats2half2_rn(lx, ly);
        g_Lhi[w] = *(uint32_t*)&hhi;
        g_Llo[w] = *(uint32_t*)&hlo;
    } else {
        float2 v = ((const float2*)R)[w];
        __half2 hhi = __floats2half2_rn(v.x, v.y);
        g_Rhi[w] = *(uint32_t*)&hhi;
    }
}

// ---------------- fp16 MMA + ldmatrix + cp.async ------------------------------
__device__ __forceinline__ void mma_f16(float* c, const uint32_t* a, uint32_t b0, uint32_t b1) {
    asm volatile(
        "mma.sync.aligned.m16n8k16.row.col.f32.f16.f16.f32 "
        "{%0,%1,%2,%3}, {%4,%5,%6,%7}, {%8,%9}, {%0,%1,%2,%3};"
        : "+f"(c[0]), "+f"(c[1]), "+f"(c[2]), "+f"(c[3])
        : "r"(a[0]), "r"(a[1]), "r"(a[2]), "r"(a[3]), "r"(b0), "r"(b1));
}

__device__ __forceinline__ void ldsm4(uint32_t* r, uint32_t addr) {
    asm volatile("ldmatrix.sync.aligned.m8n8.x4.shared.b16 {%0,%1,%2,%3}, [%4];"
                 : "=r"(r[0]), "=r"(r[1]), "=r"(r[2]), "=r"(r[3]) : "r"(addr));
}

__device__ __forceinline__ void cp16(uint32_t saddr, const void* gptr) {
    asm volatile("cp.async.cg.shared.global [%0], [%1], 16;"
                 :: "r"(saddr), "l"(gptr) : "memory");
}

// ---------------- GEMM: simT = R . L^T  (2-term fp16 split) -------------------
// C = Ahi*Bhi + Ahi*Blo. BM=BN=128, chunk=16 k, double-buffered, cp.async fill.
// Warp layout 2(m-groups) x 4(n-groups): warp tile 64m x 32n (less LDSM traffic).
#define BM 128
#define BN 128
#define SSTW 12      // padded words per smem row (48B: conflict-free for ldmatrix)
#define CSZ (128 * SSTW)

__global__ __launch_bounds__(256, 2)
void gemm_hl() {
    __shared__ uint32_t S[2][3][CSZ];   // [buf][Ahi,Bhi,Blo]

    const int bm = blockIdx.y * BM;     // rows of R
    const int bn = blockIdx.x * BN;     // rows of L
    const int tid  = threadIdx.x;
    const int warp = tid >> 5;
    const int lane = tid & 31;
    const int wm = (warp & 1) * 64;     // 2 m-groups
    const int wn = (warp >> 1) * 32;    // 4 n-groups

    const int l_row = tid >> 1;
    const int l_wb  = (tid & 1) * 4;    // word offset 0 or 4 (16B)

    const char* gAhi = (const char*)g_Rhi;   // A = R
    const char* gBhi = (const char*)g_Lhi;   // B = L
    const char* gBlo = (const char*)g_Llo;

    const uint32_t sb = (uint32_t)__cvta_generic_to_shared(&S[0][0][0]);

    auto issue_loads = [&](int c) {
        const int buf = c & 1;
        const uint32_t soff = sb + (uint32_t)(buf * 3 * CSZ + l_row * SSTW + l_wb) * 4;
        const size_t gb = ((size_t)l_row * WPR + c * 8 + l_wb) * 4;   // byte offset in row-block
        cp16(soff,               gAhi + (size_t)bm * WPR * 4 + gb);
        cp16(soff + CSZ * 4,     gBhi + (size_t)bn * WPR * 4 + gb);
        cp16(soff + 2 * CSZ * 4, gBlo + (size_t)bn * WPR * 4 + gb);
        asm volatile("cp.async.commit_group;" ::: "memory");
    };

    const uint32_t aW = (uint32_t)((wm + (lane & 15)) * SSTW + ((lane >> 4) << 2));
    const uint32_t bW = (uint32_t)((wn + (lane & 7) + ((lane >> 4) << 3)) * SSTW +
                                   (((lane >> 3) & 1) << 2));

    float acc[4][4][4];   // [im][in][q]
#pragma unroll
    for (int im = 0; im < 4; im++)
#pragma unroll
        for (int in = 0; in < 4; in++)
#pragma unroll
            for (int q = 0; q < 4; q++) acc[im][in][q] = 0.0f;

    issue_loads(0);
    asm volatile("cp.async.wait_group 0;" ::: "memory");
    __syncthreads();

    const int NCHUNK = DD / 16;   // 32
    for (int c = 0; c < NCHUNK; c++) {
        if (c + 1 < NCHUNK) issue_loads(c + 1);

        const uint32_t bufoff = (uint32_t)((c & 1) * 3 * CSZ);
        const uint32_t aHiA = sb + (bufoff + 0 * CSZ + aW) * 4;
        const uint32_t bHiA = sb + (bufoff + 1 * CSZ + bW) * 4;
        const uint32_t bLoA = sb + (bufoff + 2 * CSZ + bW) * 4;

        uint32_t afh[4][4];
#pragma unroll
        for (int im = 0; im < 4; im++)
            ldsm4(afh[im], aHiA + im * 16 * SSTW * 4);

#pragma unroll
        for (int inp = 0; inp < 2; inp++) {
            uint32_t bh[4], bl[4];
            ldsm4(bh, bHiA + inp * 16 * SSTW * 4);
            ldsm4(bl, bLoA + inp * 16 * SSTW * 4);
#pragma unroll
            for (int s = 0; s < 2; s++) {
                const int in = inp * 2 + s;
#pragma unroll
                for (int im = 0; im < 4; im++) {
                    mma_f16(acc[im][in], afh[im], bh[2 * s], bh[2 * s + 1]);  // hi*hi
                    mma_f16(acc[im][in], afh[im], bl[2 * s], bl[2 * s + 1]);  // hi*lo
                }
            }
        }

        if (c + 1 < NCHUNK) {
            asm volatile("cp.async.wait_group 0;" ::: "memory");
        }
        __syncthreads();
    }

    // epilogue
#pragma unroll
    for (int im = 0; im < 4; im++) {
#pragma unroll
        for (int in = 0; in < 4; in++) {
            int m = bm + wm + im * 16 + (lane >> 2);
            int n = bn + wn + in * 8 + 2 * (lane & 3);
            *(float2*)&g_simT[(size_t)m * NN + n]       = make_float2(acc[im][in][0], acc[im][in][1]);
            *(float2*)&g_simT[(size_t)(m + 8) * NN + n] = make_float2(acc[im][in][2], acc[im][in][3]);
        }
    }
}

// ---------------- top-10 insertion (t ascending; t[0] = current min) ----------
__device__ __forceinline__ void insert10(float* t, float v) {
    if (v > t[0]) {
        t[0] = v;
#pragma unroll
        for (int i = 0; i < 9; i++) {
            if (t[i] > t[i + 1]) { float tmp = t[i]; t[i] = t[i + 1]; t[i + 1] = tmp; }
        }
    }
}

#define SENT (-1e30f)

// ---------------- RL: per-row top-10 mean of simT ----------------------------
__global__ __launch_bounds__(256)
void row_topk_mean() {
    __shared__ float s[256 * 10];
    const int row = blockIdx.x;
    const int tid = threadIdx.x;
    const float4* p = (const float4*)(g_simT + (size_t)row * NN);

    float t[10];
#pragma unroll
    for (int i = 0; i < 10; i++) t[i] = SENT;

    for (int j = tid; j < NN / 4; j += 256) {
        float4 v = p[j];
        insert10(t, v.x); insert10(t, v.y); insert10(t, v.z); insert10(t, v.w);
    }
#pragma unroll
    for (int i = 0; i < 10; i++) s[tid * 10 + i] = t[i];
    __syncthreads();

    if (tid < 32) {
#pragma unroll
        for (int i = 0; i < 10; i++) t[i] = s[tid * 10 + i];
        for (int src = tid + 32; src < 256; src += 32)
#pragma unroll
            for (int i = 0; i < 10; i++) insert10(t, s[src * 10 + i]);
#pragma unroll
        for (int i = 0; i < 10; i++) s[tid * 10 + i] = t[i];
    }
    __syncthreads();

    if (tid == 0) {
#pragma unroll
        for (int i = 0; i < 10; i++) t[i] = s[i];
        for (int src = 1; src < 32; src++)
#pragma unroll
            for (int i = 0; i < 10; i++) insert10(t, s[src * 10 + i]);
        float sum = 0.0f;
#pragma unroll
        for (int i = 0; i < 10; i++) sum += t[i];
        g_RL[row] = sum * 0.1f;
    }
}

// ---------------- LR stage 1: per-segment column top-10 -----------------------
__global__ __launch_bounds__(256)
void col_topk_part() {
    const int col = blockIdx.x * 256 + threadIdx.x;
    const int seg = blockIdx.y;

    float t[10];
#pragma unroll
    for (int i = 0; i < 10; i++) t[i] = SENT;

    const float* base = g_simT + (size_t)seg * (NN / NSEG) * NN + col;
#pragma unroll 1
    for (int r = 0; r < NN / NSEG; r += 8) {
        float v0 = base[(size_t)(r + 0) * NN];
        float v1 = base[(size_t)(r + 1) * NN];
        float v2 = base[(size_t)(r + 2) * NN];
        float v3 = base[(size_t)(r + 3) * NN];
        float v4 = base[(size_t)(r + 4) * NN];
        float v5 = base[(size_t)(r + 5) * NN];
        float v6 = base[(size_t)(r + 6) * NN];
        float v7 = base[(size_t)(r + 7) * NN];
        insert10(t, v0); insert10(t, v1); insert10(t, v2); insert10(t, v3);
        insert10(t, v4); insert10(t, v5); insert10(t, v6); insert10(t, v7);
    }
#pragma unroll
    for (int i = 0; i < 10; i++) g_part[seg][col][i] = t[i];
}

// ---------------- LR stage 2: merge segments; P = LR + RL ---------------------
__global__ __launch_bounds__(256)
void col_topk_reduce() {
    const int col = blockIdx.x * 256 + threadIdx.x;
    float t[10];
#pragma unroll
    for (int i = 0; i < 10; i++) t[i] = g_part[0][col][i];
#pragma unroll 1
    for (int seg = 1; seg < NSEG; seg++) {
        if (g_part[seg][col][9] > t[0])
#pragma unroll
            for (int i = 0; i < 10; i++) insert10(t, g_part[seg][col][i]);
    }
    float sum = 0.0f;
#pragma unroll
    for (int i = 0; i < 10; i++) sum += t[i];
    g_P[col] = sum * 0.1f + g_RL[col];   // P = LR + RL
}

// ---------------- rank + top1 over csls rows ---------------------------------
__global__ __launch_bounds__(256)
void rank_top1(float* __restrict__ ranks, float* __restrict__ top1) {
    __shared__ int   s_gt[256];
    __shared__ int   s_eq[256];
    __shared__ float s_mx[256];

    const int i   = blockIdx.x;
    const int tid = threadIdx.x;
    const float* prow = g_simT + (size_t)i * NN;
    const float d = 2.0f * prow[i] - g_P[i];

    int cnt_gt = 0, cnt_eq = 0;
    float mx = SENT;

    const float4* pv = (const float4*)prow;
    const float4* qv = (const float4*)g_P;
    for (int j4 = tid; j4 < NN / 4; j4 += 256) {
        float4 v = pv[j4];
        float4 q = qv[j4];
        int j = j4 * 4;
        float c0 = 2.0f * v.x - q.x;
        float c1 = 2.0f * v.y - q.y;
        float c2 = 2.0f * v.z - q.z;
        float c3 = 2.0f * v.w - q.w;
        cnt_gt += (c0 > d) + (c1 > d) + (c2 > d) + (c3 > d);
        if (c0 == d && (j + 0) < i) cnt_eq++;
        if (c1 == d && (j + 1) < i) cnt_eq++;
        if (c2 == d && (j + 2) < i) cnt_eq++;
        if (c3 == d && (j + 3) < i) cnt_eq++;
        mx = fmaxf(mx, fmaxf(fmaxf(c0, c1), fmaxf(c2, c3)));
    }

    s_gt[tid] = cnt_gt; s_eq[tid] = cnt_eq; s_mx[tid] = mx;
    __syncthreads();
    for (int str = 128; str > 0; str >>= 1) {
        if (tid < str) {
            s_gt[tid] += s_gt[tid + str];
            s_eq[tid] += s_eq[tid + str];
            s_mx[tid] = fmaxf(s_mx[tid], s_mx[tid + str]);
        }
        __syncthreads();
    }
    if (tid == 0) {
        ranks[i] = (float)(s_gt[0] + s_eq[0]);
        top1[i]  = s_mx[0];
    }
}

// ---------------- launch (sequential; overlap experiments reverted) -----------
extern "C" void kernel_launch(void* const* d_in, const int* in_sizes, int n_in,
                              void* d_out, int out_size) {
    const float* L = (const float*)d_in[0];
    const float* R = (const float*)d_in[1];

    dim3 cgrid(NN * WPR / 256, 2);
    cvt_hl<<<cgrid, 256>>>(L, R);

    dim3 grid(NN / BN, NN / BM);
    gemm_hl<<<grid, 256>>>();

    row_topk_mean<<<NN, 256>>>();                    // RL over simT rows
    col_topk_part<<<dim3(NN / 256, NSEG), 256>>>();  // LR stage 1
    col_topk_reduce<<<NN / 256, 256>>>();            // LR stage 2 + P

    float* ranks = (float*)d_out;
    float* top1  = (float*)d_out + NN;
    rank_top1<<<NN, 256>>>(ranks, top1);
}